// round 7
// baseline (speedup 1.0000x reference)
#include <cuda_runtime.h>
#include <cuda_bf16.h>
#include <cstddef>

#define DD 128
#define MAXN 100000
#define MAXE 1000000
#define SPAD 136   // smem row stride (floats): perm-layout -> perfect 2-phase LDS.64

// ---- scratch (no cudaMalloc allowed) ----
__device__ float g_aggr[(size_t)MAXN * DD];
__device__ float g_z1[(size_t)MAXN * DD];
__device__ float g_z2[(size_t)MAXN * DD];
__device__ int   g_idx[(size_t)2 * MAXE];
__device__ int   g_fmt;
__device__ float g_sum[DD];
__device__ float g_sq[DD];
__device__ float g_s1[DD];
__device__ float g_c1[DD];
__device__ float g_sh[DD];
__device__ float g_ch[DD];

// ---------------------------------------------------------------- edge fmt detect (parallel)
__global__ void detect_kernel(const int* __restrict__ ei32, int E) {
    __shared__ int bad;
    if (threadIdx.x == 0) bad = 0;
    __syncthreads();
    long long e = (long long)(threadIdx.x + 1) * (2LL * E) / 66;
    if (ei32[2 * (e >> 1) + 1] != 0) bad = 1;
    __syncthreads();
    if (threadIdx.x == 0) g_fmt = !bad;
}

__global__ void convert_kernel(const void* __restrict__ ei, int n2, int N) {
    int i = blockIdx.x * blockDim.x + threadIdx.x;
    if (i >= n2) return;
    int v;
    if (g_fmt) v = (int)((const long long*)ei)[i];
    else       v = ((const int*)ei)[i];
    if (v < 0) v = 0;
    if (v >= N) v = N - 1;
    g_idx[i] = v;
}

// ---------------------------------------------------------------- aggr init
__global__ void init_kernel(const float4* __restrict__ h, float4* __restrict__ aggr,
                            const float* __restrict__ s, const float* __restrict__ c,
                            const float* __restrict__ epsP, int layer, int mode, int n4) {
    int i = blockIdx.x * blockDim.x + threadIdx.x;
    if (i >= n4) return;
    float ev = 1.0f + epsP[layer];
    float4 v = h[i];
    if (mode) {
        int k = (i & 31) * 4;
        v.x = fmaxf(fmaf(s[k + 0], v.x, c[k + 0]), 0.f);
        v.y = fmaxf(fmaf(s[k + 1], v.y, c[k + 1]), 0.f);
        v.z = fmaxf(fmaf(s[k + 2], v.z, c[k + 2]), 0.f);
        v.w = fmaxf(fmaf(s[k + 3], v.w, c[k + 3]), 0.f);
    }
    aggr[i] = make_float4(ev * v.x, ev * v.y, ev * v.z, ev * v.w);
}

// ---------------------------------------------------------------- scatter (red.global.v4)
__global__ void scatter_kernel(const float4* __restrict__ h,
                               const int* __restrict__ idx, int E,
                               float* __restrict__ aggr,
                               const float* __restrict__ sH,
                               const float* __restrict__ cH, int mode) {
    __shared__ float ss[DD], sc[DD];
    if (mode) {
        if (threadIdx.x < DD) { ss[threadIdx.x] = sH[threadIdx.x]; sc[threadIdx.x] = cH[threadIdx.x]; }
        __syncthreads();
    }
    int gt = blockIdx.x * blockDim.x + threadIdx.x;
    int e = gt >> 5;
    if (e >= E) return;
    int lane = gt & 31;
    int src = idx[e];
    int dst = idx[E + e];
    float4 v = h[(size_t)src * 32 + lane];
    int k = lane * 4;
    if (mode) {
        v.x = fmaf(ss[k + 0], v.x, sc[k + 0]);
        v.y = fmaf(ss[k + 1], v.y, sc[k + 1]);
        v.z = fmaf(ss[k + 2], v.z, sc[k + 2]);
        v.w = fmaf(ss[k + 3], v.w, sc[k + 3]);
    }
    v.x = fmaxf(v.x, 0.f); v.y = fmaxf(v.y, 0.f);
    v.z = fmaxf(v.z, 0.f); v.w = fmaxf(v.w, 0.f);
    if (v.x != 0.f || v.y != 0.f || v.z != 0.f || v.w != 0.f) {
        float* o = aggr + (size_t)dst * DD + k;
        asm volatile("red.global.add.v4.f32 [%0], {%1, %2, %3, %4};"
                     :: "l"(o), "f"(v.x), "f"(v.y), "f"(v.z), "f"(v.w) : "memory");
    }
}

// ---------------------------------------------------------------- 3xTF32 helpers
__device__ __forceinline__ unsigned f2tf(float x) {
    unsigned r;
    asm("cvt.rna.tf32.f32 %0, %1;" : "=r"(r) : "f"(x));
    return r;
}
__device__ __forceinline__ void mma8(float* c, unsigned a0, unsigned a1, unsigned a2, unsigned a3,
                                     unsigned b0, unsigned b1) {
    asm volatile(
        "mma.sync.aligned.m16n8k8.row.col.f32.tf32.tf32.f32 "
        "{%0,%1,%2,%3},{%4,%5,%6,%7},{%8,%9},{%0,%1,%2,%3};"
        : "+f"(c[0]), "+f"(c[1]), "+f"(c[2]), "+f"(c[3])
        : "r"(a0), "r"(a1), "r"(a2), "r"(a3), "r"(b0), "r"(b1));
}
// permuted k index: k = kt*8 + q + 4*h  ->  kt*8 + q*2 + h  (fragment pair contiguous)
__device__ __forceinline__ int kperm(int k) {
    return ((k >> 3) << 3) + ((k & 3) << 1) + ((k >> 2) & 1);
}

// ---------------------------------------------------------------- GEMM (3xTF32, cvt-free mainloop)
// out[row][j] = sum_k a(row,k) * W[j][k] + bias[j]
// mode 0: a = Ab;  mode 2: a = relu(sIn*Ab+cIn)
__global__ void __launch_bounds__(256, 1) gemm_tf32(
    const float* __restrict__ Ab,
    const float* __restrict__ W, const float* __restrict__ bias,
    const float* __restrict__ sIn, const float* __restrict__ cIn,
    int mode, int M,
    float* __restrict__ Z, float* __restrict__ gsum, float* __restrict__ gsq) {
    extern __shared__ float sm[];
    float*    As  = sm;                          // [row][perm k] 128 x SPAD
    unsigned* Whi = (unsigned*)(As + 128 * SPAD);   // [n][perm k]
    unsigned* Wlo = Whi + 128 * SPAD;
    float* csum = (float*)(Wlo + 128 * SPAD);    // 128
    float* csq  = csum + DD;                     // 128

    const int tid = threadIdx.x;
    const int lane = tid & 31, wid = tid >> 5;
    const int rowBase = blockIdx.x << 7;

    if (tid < DD) { csum[tid] = 0.f; csq[tid] = 0.f; }

    // W -> Whi/Wlo (tf32 hi + tf32 residual), permuted layout
    for (int t = 0; t < 64; t++) {
        int i = tid + t * 256;
        int n = i >> 7, k = i & 127;
        float w = W[i];
        unsigned hi = f2tf(w);
        unsigned lo = f2tf(w - __uint_as_float(hi));
        int off = n * SPAD + kperm(k);
        Whi[off] = hi;
        Wlo[off] = lo;
    }
    // A -> As (fused pre-op), permuted layout
    for (int t = 0; t < 16; t++) {
        int i = tid + t * 256;           // 4096 float4
        int row = i >> 5, kq = (i & 31) * 4;
        float4 v = make_float4(0.f, 0.f, 0.f, 0.f);
        int gr = rowBase + row;
        if (gr < M) {
            v = *(const float4*)(Ab + (size_t)gr * DD + kq);
            if (mode == 2) {
                v.x = fmaxf(fmaf(sIn[kq + 0], v.x, cIn[kq + 0]), 0.f);
                v.y = fmaxf(fmaf(sIn[kq + 1], v.y, cIn[kq + 1]), 0.f);
                v.z = fmaxf(fmaf(sIn[kq + 2], v.z, cIn[kq + 2]), 0.f);
                v.w = fmaxf(fmaf(sIn[kq + 3], v.w, cIn[kq + 3]), 0.f);
            }
        }
        // k = kq..kq+3: same kt (kq>>3), same h ((kq>>2)&1), q = 0..3 -> stride 2
        float* p = As + row * SPAD + ((kq >> 3) << 3) + ((kq >> 2) & 1);
        p[0] = v.x; p[2] = v.y; p[4] = v.z; p[6] = v.w;
    }
    __syncthreads();

    const int q = lane & 3, mr = lane >> 2;
    const int mw = wid * 16;             // 16 rows per warp

    float acc[16][4];
#pragma unroll
    for (int nt = 0; nt < 16; nt++)
#pragma unroll
        for (int j = 0; j < 4; j++) acc[nt][j] = 0.f;

    const float*    aBase0 = As + (mw + mr) * SPAD + q * 2;
    const float*    aBase1 = aBase0 + 8 * SPAD;
    const unsigned* bhBase = Whi + mr * SPAD + q * 2;
    const unsigned* blBase = Wlo + mr * SPAD + q * 2;

    for (int kt = 0; kt < 16; kt++) {
        const int k8 = kt * 8;
        float2 aA = *(const float2*)(aBase0 + k8);   // (a0, a2): row mr,   k0+q / k0+q+4
        float2 aB = *(const float2*)(aBase1 + k8);   // (a1, a3): row mr+8
        unsigned aH0 = f2tf(aA.x), aH2 = f2tf(aA.y);
        unsigned aH1 = f2tf(aB.x), aH3 = f2tf(aB.y);
        unsigned aL0 = __float_as_uint(aA.x - __uint_as_float(aH0));
        unsigned aL2 = __float_as_uint(aA.y - __uint_as_float(aH2));
        unsigned aL1 = __float_as_uint(aB.x - __uint_as_float(aH1));
        unsigned aL3 = __float_as_uint(aB.y - __uint_as_float(aH3));
#pragma unroll
        for (int nt = 0; nt < 16; nt++) {
            const int boff = nt * 8 * SPAD + k8;
            uint2 bh = *(const uint2*)(bhBase + boff);
            uint2 bl = *(const uint2*)(blBase + boff);
            mma8(acc[nt], aH0, aH1, aH2, aH3, bh.x, bh.y);
            mma8(acc[nt], aL0, aL1, aL2, aL3, bh.x, bh.y);
            mma8(acc[nt], aH0, aH1, aH2, aH3, bl.x, bl.y);
        }
    }

    // epilogue: bias, store Z, per-feature stats
    const int r0 = rowBase + mw + mr;
    const int r1 = r0 + 8;
#pragma unroll
    for (int nt = 0; nt < 16; nt++) {
        int j0 = nt * 8 + 2 * q;
        float bx = bias[j0], by = bias[j0 + 1];
        float v00 = acc[nt][0] + bx, v01 = acc[nt][1] + by;
        float v10 = acc[nt][2] + bx, v11 = acc[nt][3] + by;
        bool ok0 = r0 < M, ok1 = r1 < M;
        if (ok0) *(float2*)(Z + (size_t)r0 * DD + j0) = make_float2(v00, v01);
        if (ok1) *(float2*)(Z + (size_t)r1 * DD + j0) = make_float2(v10, v11);
        float s0 = (ok0 ? v00 : 0.f) + (ok1 ? v10 : 0.f);
        float s1 = (ok0 ? v01 : 0.f) + (ok1 ? v11 : 0.f);
        float q0 = (ok0 ? v00 * v00 : 0.f) + (ok1 ? v10 * v10 : 0.f);
        float q1 = (ok0 ? v01 * v01 : 0.f) + (ok1 ? v11 * v11 : 0.f);
#pragma unroll
        for (int m = 4; m <= 16; m <<= 1) {
            s0 += __shfl_xor_sync(0xffffffff, s0, m);
            s1 += __shfl_xor_sync(0xffffffff, s1, m);
            q0 += __shfl_xor_sync(0xffffffff, q0, m);
            q1 += __shfl_xor_sync(0xffffffff, q1, m);
        }
        if (mr == 0) {
            atomicAdd(&csum[j0], s0);
            atomicAdd(&csum[j0 + 1], s1);
            atomicAdd(&csq[j0], q0);
            atomicAdd(&csq[j0 + 1], q1);
        }
    }
    __syncthreads();
    if (tid < DD) {
        atomicAdd(&gsum[tid], csum[tid]);
        atomicAdd(&gsq[tid], csq[tid]);
    }
}

// ---------------------------------------------------------------- BN finalize
__global__ void finalize_kernel(float* __restrict__ gsum, float* __restrict__ gsq,
                                const float* __restrict__ gamma, const float* __restrict__ beta,
                                float invM, float* __restrict__ sOut, float* __restrict__ cOut) {
    int j = threadIdx.x;
    float mean = gsum[j] * invM;
    float var = gsq[j] * invM - mean * mean;
    float s = gamma[j] * rsqrtf(var + 1e-5f);
    sOut[j] = s;
    cOut[j] = beta[j] - mean * s;
    gsum[j] = 0.f;
    gsq[j] = 0.f;
}

// ---------------------------------------------------------------- final apply
__global__ void apply_kernel(const float4* __restrict__ z, const float* __restrict__ s,
                             const float* __restrict__ c, float4* __restrict__ out, int n4) {
    int i = blockIdx.x * blockDim.x + threadIdx.x;
    if (i >= n4) return;
    int k = (i & 31) * 4;
    float4 v = z[i];
    out[i] = make_float4(fmaf(s[k + 0], v.x, c[k + 0]),
                         fmaf(s[k + 1], v.y, c[k + 1]),
                         fmaf(s[k + 2], v.z, c[k + 2]),
                         fmaf(s[k + 3], v.w, c[k + 3]));
}

// ---------------------------------------------------------------- launch
extern "C" void kernel_launch(void* const* d_in, const int* in_sizes, int n_in,
                              void* d_out, int out_size) {
    const float* x    = (const float*)d_in[0];
    const void*  ei   = d_in[1];
    const float* W1   = (const float*)d_in[2];
    const float* b1   = (const float*)d_in[3];
    const float* g1   = (const float*)d_in[4];
    const float* bt1  = (const float*)d_in[5];
    const float* W2   = (const float*)d_in[6];
    const float* b2   = (const float*)d_in[7];
    const float* epsv = (const float*)d_in[8];
    const float* gout = (const float*)d_in[9];
    const float* bout = (const float*)d_in[10];

    int N = in_sizes[0] / DD;
    int E = in_sizes[1] / 2;

    void* p;
    cudaGetSymbolAddress(&p, g_aggr); float* aggr = (float*)p;
    cudaGetSymbolAddress(&p, g_z1);   float* z1   = (float*)p;
    cudaGetSymbolAddress(&p, g_z2);   float* z2   = (float*)p;
    cudaGetSymbolAddress(&p, g_idx);  int*   idx  = (int*)p;
    cudaGetSymbolAddress(&p, g_sum);  float* gsum = (float*)p;
    cudaGetSymbolAddress(&p, g_sq);   float* gsq  = (float*)p;
    cudaGetSymbolAddress(&p, g_s1);   float* s1   = (float*)p;
    cudaGetSymbolAddress(&p, g_c1);   float* c1   = (float*)p;
    cudaGetSymbolAddress(&p, g_sh);   float* sh   = (float*)p;
    cudaGetSymbolAddress(&p, g_ch);   float* ch   = (float*)p;

    constexpr int SMEM = (3 * 128 * SPAD + 2 * DD) * 4;
    cudaFuncSetAttribute(gemm_tf32, cudaFuncAttributeMaxDynamicSharedMemorySize, SMEM);

    float invM = 1.0f / (float)N;
    int n4 = N * (DD / 4);
    int zb = (n4 + 255) / 256;
    long long sthreads = (long long)E * 32;
    int sb = (int)((sthreads + 255) / 256);
    int gb = (N + 127) / 128;
    int n2 = 2 * E;
    int cb = (n2 + 255) / 256;

    detect_kernel<<<1, 64>>>((const int*)ei, E);
    convert_kernel<<<cb, 256>>>(ei, n2, N);

    // ---- layer 0 ----
    init_kernel<<<zb, 256>>>((const float4*)x, (float4*)aggr, nullptr, nullptr, epsv, 0, 0, n4);
    scatter_kernel<<<sb, 256>>>((const float4*)x, idx, E, aggr, nullptr, nullptr, 0);
    gemm_tf32<<<gb, 256, SMEM>>>(aggr, W1, b1, nullptr, nullptr, 0, N, z1, gsum, gsq);
    finalize_kernel<<<1, DD>>>(gsum, gsq, g1, bt1, invM, s1, c1);
    gemm_tf32<<<gb, 256, SMEM>>>(z1, W2, b2, s1, c1, 2, N, z2, gsum, gsq);
    finalize_kernel<<<1, DD>>>(gsum, gsq, gout, bout, invM, sh, ch);

    // ---- layer 1 ----
    init_kernel<<<zb, 256>>>((const float4*)z2, (float4*)aggr, sh, ch, epsv, 1, 1, n4);
    scatter_kernel<<<sb, 256>>>((const float4*)z2, idx, E, aggr, sh, ch, 1);
    gemm_tf32<<<gb, 256, SMEM>>>(aggr, W1 + DD * DD, b1 + DD, nullptr, nullptr, 0, N, z1, gsum, gsq);
    finalize_kernel<<<1, DD>>>(gsum, gsq, g1 + DD, bt1 + DD, invM, s1, c1);
    gemm_tf32<<<gb, 256, SMEM>>>(z1, W2 + DD * DD, b2 + DD, s1, c1, 2, N, z2, gsum, gsq);
    finalize_kernel<<<1, DD>>>(gsum, gsq, gout + DD, bout + DD, invM, sh, ch);

    apply_kernel<<<zb, 256>>>((const float4*)z2, sh, ch, (float4*)d_out, n4);
}

// round 9
// speedup vs baseline: 1.3473x; 1.3473x over previous
#include <cuda_runtime.h>
#include <cuda_bf16.h>
#include <cstddef>

#define DD 128
#define MAXN 100000
#define MAXE 1000000
#define WPAD 132   // smem row stride: %4==0 -> 16B-aligned rows for LDS.128; not %32 -> de-conflicted banks

// ---- scratch (no cudaMalloc allowed) ----
__device__ float g_aggr[(size_t)MAXN * DD];
__device__ float g_z1[(size_t)MAXN * DD];
__device__ float g_z2[(size_t)MAXN * DD];
__device__ int   g_idx[(size_t)2 * MAXE];   // canonical int32 [src(E), dst(E)]
__device__ int   g_fmt;
__device__ int   g_cnt[MAXN];
__device__ int   g_off[MAXN + 1];
__device__ int   g_cur[MAXN];
__device__ int   g_srcl[MAXE];              // CSR: src lists grouped by dst
__device__ int   g_bsum[512];
__device__ float g_sum[DD];
__device__ float g_sq[DD];
__device__ float g_s1[DD];
__device__ float g_c1[DD];
__device__ float g_sh[DD];
__device__ float g_ch[DD];

// ---------------------------------------------------------------- edge fmt detect
__global__ void detect_kernel(const int* __restrict__ ei32, int E) {
    __shared__ int bad;
    if (threadIdx.x == 0) bad = 0;
    __syncthreads();
    long long e = (long long)(threadIdx.x + 1) * (2LL * E) / 66;
    if (ei32[2 * (e >> 1) + 1] != 0) bad = 1;
    __syncthreads();
    if (threadIdx.x == 0) g_fmt = !bad;
}
__global__ void convert_kernel(const void* __restrict__ ei, int n2, int N) {
    int i = blockIdx.x * blockDim.x + threadIdx.x;
    if (i >= n2) return;
    int v = g_fmt ? (int)((const long long*)ei)[i] : ((const int*)ei)[i];
    if (v < 0) v = 0;
    if (v >= N) v = N - 1;
    g_idx[i] = v;
}

// ---------------------------------------------------------------- CSR build
__global__ void zcnt_kernel(int* __restrict__ cnt, int N) {
    int i = blockIdx.x * blockDim.x + threadIdx.x;
    if (i < N) cnt[i] = 0;
}
__global__ void hist_kernel(const int* __restrict__ idx, int E, int* __restrict__ cnt) {
    int e = blockIdx.x * blockDim.x + threadIdx.x;
    if (e < E) atomicAdd(&cnt[idx[E + e]], 1);
}
__global__ void scan_block(const int* __restrict__ cnt, int n, int* __restrict__ part,
                           int* __restrict__ bsum) {
    __shared__ int s[256];
    int i = blockIdx.x * 256 + threadIdx.x;
    int v = (i < n) ? cnt[i] : 0;
    s[threadIdx.x] = v;
    __syncthreads();
    for (int d = 1; d < 256; d <<= 1) {
        int t = (threadIdx.x >= d) ? s[threadIdx.x - d] : 0;
        __syncthreads();
        s[threadIdx.x] += t;
        __syncthreads();
    }
    if (i < n) part[i] = s[threadIdx.x];
    if (threadIdx.x == 255) bsum[blockIdx.x] = s[255];
}
__global__ void scan_sums(int* __restrict__ bsum, int nb) {
    __shared__ int s[512];
    int v = (threadIdx.x < nb) ? bsum[threadIdx.x] : 0;
    s[threadIdx.x] = v;
    __syncthreads();
    for (int d = 1; d < 512; d <<= 1) {
        int t = (threadIdx.x >= d) ? s[threadIdx.x - d] : 0;
        __syncthreads();
        s[threadIdx.x] += t;
        __syncthreads();
    }
    if (threadIdx.x < nb) bsum[threadIdx.x] = s[threadIdx.x];
}
__global__ void scan_final(const int* __restrict__ part, const int* __restrict__ bsum,
                           const int* __restrict__ cnt, int n,
                           int* __restrict__ off, int* __restrict__ cur) {
    int i = blockIdx.x * 256 + threadIdx.x;
    if (i >= n) return;
    int add = (blockIdx.x > 0) ? bsum[blockIdx.x - 1] : 0;
    int v = part[i] + add;          // inclusive
    off[i + 1] = v;
    cur[i] = v - cnt[i];            // exclusive
    if (i == 0) off[0] = 0;
}
__global__ void fill_kernel(const int* __restrict__ idx, int E,
                            int* __restrict__ cur, int* __restrict__ srcl) {
    int e = blockIdx.x * blockDim.x + threadIdx.x;
    if (e >= E) return;
    int pos = atomicAdd(&cur[idx[E + e]], 1);
    srcl[pos] = idx[e];
}

// ---------------------------------------------------------------- aggregate (pull, warp/dst)
// mode 0: aggr[d] = ev*h[d]                  + sum_{s in N(d)} relu(h[s])
// mode 1: aggr[d] = ev*relu(aff(h[d]))       + sum_{s in N(d)} relu(aff(h[s]))
__global__ void aggregate_kernel(const float4* __restrict__ h,
                                 const int* __restrict__ off, const int* __restrict__ srcl,
                                 int N, float4* __restrict__ aggr,
                                 const float* __restrict__ sH, const float* __restrict__ cH,
                                 const float* __restrict__ epsP, int layer, int mode) {
    __shared__ float ss[DD], sc[DD];
    if (mode) {
        if (threadIdx.x < DD) { ss[threadIdx.x] = sH[threadIdx.x]; sc[threadIdx.x] = cH[threadIdx.x]; }
        __syncthreads();
    }
    int gw = (blockIdx.x * blockDim.x + threadIdx.x) >> 5;
    if (gw >= N) return;
    int lane = threadIdx.x & 31;
    int k = lane * 4;
    float ev = 1.0f + epsP[layer];
    float s0 = 0.f, s1 = 0.f, s2 = 0.f, s3 = 0.f, c0 = 0.f, c1 = 0.f, c2 = 0.f, c3 = 0.f;
    if (mode) {
        s0 = ss[k]; s1 = ss[k + 1]; s2 = ss[k + 2]; s3 = ss[k + 3];
        c0 = sc[k]; c1 = sc[k + 1]; c2 = sc[k + 2]; c3 = sc[k + 3];
    }

    // self term
    float4 a = h[(size_t)gw * 32 + lane];
    if (mode) {
        a.x = fmaxf(fmaf(s0, a.x, c0), 0.f);
        a.y = fmaxf(fmaf(s1, a.y, c1), 0.f);
        a.z = fmaxf(fmaf(s2, a.z, c2), 0.f);
        a.w = fmaxf(fmaf(s3, a.w, c3), 0.f);
    }
    float4 acc = make_float4(ev * a.x, ev * a.y, ev * a.z, ev * a.w);

    int e = off[gw], eEnd = off[gw + 1];
    // unroll-by-2 with prefetch of indices
    for (; e + 2 <= eEnd; e += 2) {
        int sA = srcl[e], sB = srcl[e + 1];
        float4 vA = h[(size_t)sA * 32 + lane];
        float4 vB = h[(size_t)sB * 32 + lane];
        if (mode) {
            vA.x = fmaf(s0, vA.x, c0); vA.y = fmaf(s1, vA.y, c1);
            vA.z = fmaf(s2, vA.z, c2); vA.w = fmaf(s3, vA.w, c3);
            vB.x = fmaf(s0, vB.x, c0); vB.y = fmaf(s1, vB.y, c1);
            vB.z = fmaf(s2, vB.z, c2); vB.w = fmaf(s3, vB.w, c3);
        }
        acc.x += fmaxf(vA.x, 0.f) + fmaxf(vB.x, 0.f);
        acc.y += fmaxf(vA.y, 0.f) + fmaxf(vB.y, 0.f);
        acc.z += fmaxf(vA.z, 0.f) + fmaxf(vB.z, 0.f);
        acc.w += fmaxf(vA.w, 0.f) + fmaxf(vB.w, 0.f);
    }
    if (e < eEnd) {
        int sA = srcl[e];
        float4 vA = h[(size_t)sA * 32 + lane];
        if (mode) {
            vA.x = fmaf(s0, vA.x, c0); vA.y = fmaf(s1, vA.y, c1);
            vA.z = fmaf(s2, vA.z, c2); vA.w = fmaf(s3, vA.w, c3);
        }
        acc.x += fmaxf(vA.x, 0.f);
        acc.y += fmaxf(vA.y, 0.f);
        acc.z += fmaxf(vA.z, 0.f);
        acc.w += fmaxf(vA.w, 0.f);
    }
    aggr[(size_t)gw * 32 + lane] = acc;
}

// ---------------------------------------------------------------- GEMM (FFMA, proven 774.9 config)
// out[row][j] = sum_k a(row,k) * W[j][k] + bias[j]
// mode 0: a = Ab;  mode 2: a = relu(sIn*Ab+cIn)
__global__ void __launch_bounds__(256, 2) gemm_kernel(
    const float* __restrict__ Ab,
    const float* __restrict__ W, const float* __restrict__ bias,
    const float* __restrict__ sIn, const float* __restrict__ cIn,
    int mode, int M,
    float* __restrict__ Z, float* __restrict__ gsum, float* __restrict__ gsq) {
    extern __shared__ float sm[];
    float* Ws = sm;
    float* As = Ws + 128 * WPAD;
    float* csum = As + 2 * 16 * WPAD;
    float* csq = csum + DD;

    const int tid = threadIdx.x;
    for (int i = tid; i < DD * DD; i += 256) {
        int j = i >> 7, k = i & 127;
        Ws[k * WPAD + j] = W[i];
    }
    if (tid < DD) { csum[tid] = 0.f; csq[tid] = 0.f; }

    const int tx = tid & 15, ty = tid >> 4;
    const int rowBase = blockIdx.x << 7;

    const int m0 = tid >> 2;
    const int kq = tid & 3;

    float acc[64];
#pragma unroll
    for (int i = 0; i < 64; i++) acc[i] = 0.f;

    float4 ra[2];

    auto loadChunk = [&](int c) {
        int kbase = c * 16 + kq * 4;
#pragma unroll
        for (int h2 = 0; h2 < 2; h2++) {
            int row = rowBase + m0 + h2 * 64;
            float4 v = make_float4(0.f, 0.f, 0.f, 0.f);
            if (row < M) {
                v = *(const float4*)(Ab + (size_t)row * DD + kbase);
                if (mode == 2) {
                    v.x = fmaxf(fmaf(sIn[kbase + 0], v.x, cIn[kbase + 0]), 0.f);
                    v.y = fmaxf(fmaf(sIn[kbase + 1], v.y, cIn[kbase + 1]), 0.f);
                    v.z = fmaxf(fmaf(sIn[kbase + 2], v.z, cIn[kbase + 2]), 0.f);
                    v.w = fmaxf(fmaf(sIn[kbase + 3], v.w, cIn[kbase + 3]), 0.f);
                }
            }
            ra[h2] = v;
        }
    };
    auto storeChunk = [&](int buf) {
        float* p = As + buf * (16 * WPAD);
#pragma unroll
        for (int h2 = 0; h2 < 2; h2++) {
            int m = m0 + h2 * 64;
            p[(kq * 4 + 0) * WPAD + m] = ra[h2].x;
            p[(kq * 4 + 1) * WPAD + m] = ra[h2].y;
            p[(kq * 4 + 2) * WPAD + m] = ra[h2].z;
            p[(kq * 4 + 3) * WPAD + m] = ra[h2].w;
        }
    };

    loadChunk(0);
    storeChunk(0);
    __syncthreads();

    for (int c = 0; c < 8; c++) {
        if (c < 7) loadChunk(c + 1);
        float* pA = As + (c & 1) * (16 * WPAD);
#pragma unroll
        for (int kk = 0; kk < 16; kk++) {
            float af[8], bf[8];
            *(float4*)(af)     = *(const float4*)(pA + kk * WPAD + ty * 8);
            *(float4*)(af + 4) = *(const float4*)(pA + kk * WPAD + ty * 8 + 4);
            int kg = c * 16 + kk;
            *(float4*)(bf)     = *(const float4*)(Ws + kg * WPAD + tx * 8);
            *(float4*)(bf + 4) = *(const float4*)(Ws + kg * WPAD + tx * 8 + 4);
#pragma unroll
            for (int i = 0; i < 8; i++)
#pragma unroll
                for (int j = 0; j < 8; j++)
                    acc[i * 8 + j] = fmaf(af[i], bf[j], acc[i * 8 + j]);
        }
        if (c < 7) {
            storeChunk((c + 1) & 1);
            __syncthreads();
        }
    }

    float bj[8];
#pragma unroll
    for (int j = 0; j < 8; j++) bj[j] = bias[tx * 8 + j];

    float lsum[8], lsq[8];
#pragma unroll
    for (int j = 0; j < 8; j++) { lsum[j] = 0.f; lsq[j] = 0.f; }

#pragma unroll
    for (int i = 0; i < 8; i++) {
        int row = rowBase + ty * 8 + i;
        if (row < M) {
            float v[8];
#pragma unroll
            for (int j = 0; j < 8; j++) {
                v[j] = acc[i * 8 + j] + bj[j];
                lsum[j] += v[j];
                lsq[j] = fmaf(v[j], v[j], lsq[j]);
            }
            float4* zp = (float4*)(Z + (size_t)row * DD + tx * 8);
            zp[0] = make_float4(v[0], v[1], v[2], v[3]);
            zp[1] = make_float4(v[4], v[5], v[6], v[7]);
        }
    }
#pragma unroll
    for (int j = 0; j < 8; j++) {
        atomicAdd(&csum[tx * 8 + j], lsum[j]);
        atomicAdd(&csq[tx * 8 + j], lsq[j]);
    }
    __syncthreads();
    if (tid < DD) {
        atomicAdd(&gsum[tid], csum[tid]);
        atomicAdd(&gsq[tid], csq[tid]);
    }
}

// ---------------------------------------------------------------- BN finalize
__global__ void finalize_kernel(float* __restrict__ gsum, float* __restrict__ gsq,
                                const float* __restrict__ gamma, const float* __restrict__ beta,
                                float invM, float* __restrict__ sOut, float* __restrict__ cOut) {
    int j = threadIdx.x;
    float mean = gsum[j] * invM;
    float var = gsq[j] * invM - mean * mean;
    float s = gamma[j] * rsqrtf(var + 1e-5f);
    sOut[j] = s;
    cOut[j] = beta[j] - mean * s;
    gsum[j] = 0.f;
    gsq[j] = 0.f;
}

// ---------------------------------------------------------------- final apply
__global__ void apply_kernel(const float4* __restrict__ z, const float* __restrict__ s,
                             const float* __restrict__ c, float4* __restrict__ out, int n4) {
    int i = blockIdx.x * blockDim.x + threadIdx.x;
    if (i >= n4) return;
    int k = (i & 31) * 4;
    float4 v = z[i];
    out[i] = make_float4(fmaf(s[k + 0], v.x, c[k + 0]),
                         fmaf(s[k + 1], v.y, c[k + 1]),
                         fmaf(s[k + 2], v.z, c[k + 2]),
                         fmaf(s[k + 3], v.w, c[k + 3]));
}

// ---------------------------------------------------------------- launch
extern "C" void kernel_launch(void* const* d_in, const int* in_sizes, int n_in,
                              void* d_out, int out_size) {
    const float* x    = (const float*)d_in[0];
    const void*  ei   = d_in[1];
    const float* W1   = (const float*)d_in[2];
    const float* b1   = (const float*)d_in[3];
    const float* g1   = (const float*)d_in[4];
    const float* bt1  = (const float*)d_in[5];
    const float* W2   = (const float*)d_in[6];
    const float* b2   = (const float*)d_in[7];
    const float* epsv = (const float*)d_in[8];
    const float* gout = (const float*)d_in[9];
    const float* bout = (const float*)d_in[10];

    int N = in_sizes[0] / DD;
    int E = in_sizes[1] / 2;

    void* p;
    cudaGetSymbolAddress(&p, g_aggr); float* aggr = (float*)p;
    cudaGetSymbolAddress(&p, g_z1);   float* z1   = (float*)p;
    cudaGetSymbolAddress(&p, g_z2);   float* z2   = (float*)p;
    cudaGetSymbolAddress(&p, g_idx);  int*   idx  = (int*)p;
    cudaGetSymbolAddress(&p, g_cnt);  int*   cnt  = (int*)p;
    cudaGetSymbolAddress(&p, g_off);  int*   off  = (int*)p;
    cudaGetSymbolAddress(&p, g_cur);  int*   cur  = (int*)p;
    cudaGetSymbolAddress(&p, g_srcl); int*   srcl = (int*)p;
    cudaGetSymbolAddress(&p, g_bsum); int*   bsum = (int*)p;
    cudaGetSymbolAddress(&p, g_sum);  float* gsum = (float*)p;
    cudaGetSymbolAddress(&p, g_sq);   float* gsq  = (float*)p;
    cudaGetSymbolAddress(&p, g_s1);   float* s1   = (float*)p;
    cudaGetSymbolAddress(&p, g_c1);   float* c1   = (float*)p;
    cudaGetSymbolAddress(&p, g_sh);   float* sh   = (float*)p;
    cudaGetSymbolAddress(&p, g_ch);   float* ch   = (float*)p;

    constexpr int SMEM = (128 * WPAD + 2 * 16 * WPAD + 2 * DD) * 4;
    cudaFuncSetAttribute(gemm_kernel, cudaFuncAttributeMaxDynamicSharedMemorySize, SMEM);

    float invM = 1.0f / (float)N;
    int n4 = N * (DD / 4);
    int zb = (n4 + 255) / 256;
    int gb = (N + 127) / 128;
    int n2 = 2 * E;
    int cb = (n2 + 255) / 256;
    int eb = (E + 255) / 256;
    int nb = (N + 255) / 256;      // scan blocks (<= 512 for N <= 131072)
    int ab = (N * 32 + 255) / 256; // aggregate: warp per node

    detect_kernel<<<1, 64>>>((const int*)ei, E);
    convert_kernel<<<cb, 256>>>(ei, n2, N);

    // CSR build (reused by both layers); reuse g_cur as partial-scan buffer first
    zcnt_kernel<<<nb, 256>>>(cnt, N);
    hist_kernel<<<eb, 256>>>(idx, E, cnt);
    scan_block<<<nb, 256>>>(cnt, N, cur, bsum);
    scan_sums<<<1, 512>>>(bsum, nb);
    scan_final<<<nb, 256>>>(cur, bsum, cnt, N, off, cur);
    fill_kernel<<<eb, 256>>>(idx, E, cur, srcl);

    // ---- layer 0 ----
    aggregate_kernel<<<ab, 256>>>((const float4*)x, off, srcl, N, (float4*)aggr,
                                  nullptr, nullptr, epsv, 0, 0);
    gemm_kernel<<<gb, 256, SMEM>>>(aggr, W1, b1, nullptr, nullptr, 0, N, z1, gsum, gsq);
    finalize_kernel<<<1, DD>>>(gsum, gsq, g1, bt1, invM, s1, c1);
    gemm_kernel<<<gb, 256, SMEM>>>(z1, W2, b2, s1, c1, 2, N, z2, gsum, gsq);
    finalize_kernel<<<1, DD>>>(gsum, gsq, gout, bout, invM, sh, ch);

    // ---- layer 1 ----
    aggregate_kernel<<<ab, 256>>>((const float4*)z2, off, srcl, N, (float4*)aggr,
                                  sh, ch, epsv, 1, 1);
    gemm_kernel<<<gb, 256, SMEM>>>(aggr, W1 + DD * DD, b1 + DD, nullptr, nullptr, 0, N, z1, gsum, gsq);
    finalize_kernel<<<1, DD>>>(gsum, gsq, g1 + DD, bt1 + DD, invM, s1, c1);
    gemm_kernel<<<gb, 256, SMEM>>>(z1, W2 + DD * DD, b2 + DD, s1, c1, 2, N, z2, gsum, gsq);
    finalize_kernel<<<1, DD>>>(gsum, gsq, gout + DD, bout + DD, invM, sh, ch);

    apply_kernel<<<zb, 256>>>((const float4*)z2, sh, ch, (float4*)d_out, n4);
}

// round 10
// speedup vs baseline: 2.1268x; 1.5786x over previous
#include <cuda_runtime.h>
#include <cuda_bf16.h>
#include <cstddef>

#define DD 128
#define MAXN 100000
#define MAXE 1000000
#define AST 68   // smem row stride in 32-bit words: 68%32==4 -> (4*mr+q) covers all banks

// ---- scratch (no cudaMalloc allowed) ----
__device__ float g_aggr[(size_t)MAXN * DD];
__device__ float g_z1[(size_t)MAXN * DD];
__device__ float g_z2[(size_t)MAXN * DD];
__device__ int   g_idx[(size_t)2 * MAXE];
__device__ int   g_fmt;
__device__ int   g_cnt[MAXN];
__device__ int   g_off[MAXN + 1];
__device__ int   g_cur[MAXN];
__device__ int   g_srcl[MAXE];
__device__ int   g_bsum[512];
__device__ float g_sum[DD];
__device__ float g_sq[DD];
__device__ float g_s1[DD];
__device__ float g_c1[DD];
__device__ float g_sh[DD];
__device__ float g_ch[DD];

// ---------------------------------------------------------------- edge fmt detect
__global__ void detect_kernel(const int* __restrict__ ei32, int E) {
    __shared__ int bad;
    if (threadIdx.x == 0) bad = 0;
    __syncthreads();
    long long e = (long long)(threadIdx.x + 1) * (2LL * E) / 66;
    if (ei32[2 * (e >> 1) + 1] != 0) bad = 1;
    __syncthreads();
    if (threadIdx.x == 0) g_fmt = !bad;
}
__global__ void convert_kernel(const void* __restrict__ ei, int n2, int N) {
    int i = blockIdx.x * blockDim.x + threadIdx.x;
    if (i >= n2) return;
    int v = g_fmt ? (int)((const long long*)ei)[i] : ((const int*)ei)[i];
    if (v < 0) v = 0;
    if (v >= N) v = N - 1;
    g_idx[i] = v;
}

// ---------------------------------------------------------------- CSR build
__global__ void zcnt_kernel(int* __restrict__ cnt, int N) {
    int i = blockIdx.x * blockDim.x + threadIdx.x;
    if (i < N) cnt[i] = 0;
}
__global__ void hist_kernel(const int* __restrict__ idx, int E, int* __restrict__ cnt) {
    int e = blockIdx.x * blockDim.x + threadIdx.x;
    if (e < E) atomicAdd(&cnt[idx[E + e]], 1);
}
__global__ void scan_block(const int* __restrict__ cnt, int n, int* __restrict__ part,
                           int* __restrict__ bsum) {
    __shared__ int s[256];
    int i = blockIdx.x * 256 + threadIdx.x;
    int v = (i < n) ? cnt[i] : 0;
    s[threadIdx.x] = v;
    __syncthreads();
    for (int d = 1; d < 256; d <<= 1) {
        int t = (threadIdx.x >= d) ? s[threadIdx.x - d] : 0;
        __syncthreads();
        s[threadIdx.x] += t;
        __syncthreads();
    }
    if (i < n) part[i] = s[threadIdx.x];
    if (threadIdx.x == 255) bsum[blockIdx.x] = s[255];
}
__global__ void scan_sums(int* __restrict__ bsum, int nb) {
    __shared__ int s[512];
    int v = (threadIdx.x < nb) ? bsum[threadIdx.x] : 0;
    s[threadIdx.x] = v;
    __syncthreads();
    for (int d = 1; d < 512; d <<= 1) {
        int t = (threadIdx.x >= d) ? s[threadIdx.x - d] : 0;
        __syncthreads();
        s[threadIdx.x] += t;
        __syncthreads();
    }
    if (threadIdx.x < nb) bsum[threadIdx.x] = s[threadIdx.x];
}
__global__ void scan_final(const int* __restrict__ part, const int* __restrict__ bsum,
                           const int* __restrict__ cnt, int n,
                           int* __restrict__ off, int* __restrict__ cur) {
    int i = blockIdx.x * 256 + threadIdx.x;
    if (i >= n) return;
    int add = (blockIdx.x > 0) ? bsum[blockIdx.x - 1] : 0;
    int v = part[i] + add;
    off[i + 1] = v;
    cur[i] = v - cnt[i];
    if (i == 0) off[0] = 0;
}
__global__ void fill_kernel(const int* __restrict__ idx, int E,
                            int* __restrict__ cur, int* __restrict__ srcl) {
    int e = blockIdx.x * blockDim.x + threadIdx.x;
    if (e >= E) return;
    int pos = atomicAdd(&cur[idx[E + e]], 1);
    srcl[pos] = idx[e];
}

// ---------------------------------------------------------------- aggregate (pull, warp/dst)
__global__ void aggregate_kernel(const float4* __restrict__ h,
                                 const int* __restrict__ off, const int* __restrict__ srcl,
                                 int N, float4* __restrict__ aggr,
                                 const float* __restrict__ sH, const float* __restrict__ cH,
                                 const float* __restrict__ epsP, int layer, int mode) {
    __shared__ float ss[DD], sc[DD];
    if (mode) {
        if (threadIdx.x < DD) { ss[threadIdx.x] = sH[threadIdx.x]; sc[threadIdx.x] = cH[threadIdx.x]; }
        __syncthreads();
    }
    int gw = (blockIdx.x * blockDim.x + threadIdx.x) >> 5;
    if (gw >= N) return;
    int lane = threadIdx.x & 31;
    int k = lane * 4;
    float ev = 1.0f + epsP[layer];
    float s0 = 0.f, s1 = 0.f, s2 = 0.f, s3 = 0.f, c0 = 0.f, c1 = 0.f, c2 = 0.f, c3 = 0.f;
    if (mode) {
        s0 = ss[k]; s1 = ss[k + 1]; s2 = ss[k + 2]; s3 = ss[k + 3];
        c0 = sc[k]; c1 = sc[k + 1]; c2 = sc[k + 2]; c3 = sc[k + 3];
    }

    float4 a = h[(size_t)gw * 32 + lane];
    if (mode) {
        a.x = fmaxf(fmaf(s0, a.x, c0), 0.f);
        a.y = fmaxf(fmaf(s1, a.y, c1), 0.f);
        a.z = fmaxf(fmaf(s2, a.z, c2), 0.f);
        a.w = fmaxf(fmaf(s3, a.w, c3), 0.f);
    }
    float4 acc = make_float4(ev * a.x, ev * a.y, ev * a.z, ev * a.w);

    int e = off[gw], eEnd = off[gw + 1];
    for (; e + 2 <= eEnd; e += 2) {
        int sA = srcl[e], sB = srcl[e + 1];
        float4 vA = h[(size_t)sA * 32 + lane];
        float4 vB = h[(size_t)sB * 32 + lane];
        if (mode) {
            vA.x = fmaf(s0, vA.x, c0); vA.y = fmaf(s1, vA.y, c1);
            vA.z = fmaf(s2, vA.z, c2); vA.w = fmaf(s3, vA.w, c3);
            vB.x = fmaf(s0, vB.x, c0); vB.y = fmaf(s1, vB.y, c1);
            vB.z = fmaf(s2, vB.z, c2); vB.w = fmaf(s3, vB.w, c3);
        }
        acc.x += fmaxf(vA.x, 0.f) + fmaxf(vB.x, 0.f);
        acc.y += fmaxf(vA.y, 0.f) + fmaxf(vB.y, 0.f);
        acc.z += fmaxf(vA.z, 0.f) + fmaxf(vB.z, 0.f);
        acc.w += fmaxf(vA.w, 0.f) + fmaxf(vB.w, 0.f);
    }
    if (e < eEnd) {
        int sA = srcl[e];
        float4 vA = h[(size_t)sA * 32 + lane];
        if (mode) {
            vA.x = fmaf(s0, vA.x, c0); vA.y = fmaf(s1, vA.y, c1);
            vA.z = fmaf(s2, vA.z, c2); vA.w = fmaf(s3, vA.w, c3);
        }
        acc.x += fmaxf(vA.x, 0.f);
        acc.y += fmaxf(vA.y, 0.f);
        acc.z += fmaxf(vA.z, 0.f);
        acc.w += fmaxf(vA.w, 0.f);
    }
    aggr[(size_t)gw * 32 + lane] = acc;
}

// ---------------------------------------------------------------- bf16-split mma helpers
__device__ __forceinline__ void bsplit2(float f0, float f1, unsigned& hi, unsigned& lo) {
    __nv_bfloat16 h0 = __float2bfloat16(f0), h1 = __float2bfloat16(f1);
    float r0 = f0 - __bfloat162float(h0), r1 = f1 - __bfloat162float(h1);
    __nv_bfloat16 l0 = __float2bfloat16(r0), l1 = __float2bfloat16(r1);
    hi = ((unsigned)__bfloat16_as_ushort(h1) << 16) | __bfloat16_as_ushort(h0);
    lo = ((unsigned)__bfloat16_as_ushort(l1) << 16) | __bfloat16_as_ushort(l0);
}
__device__ __forceinline__ void mma16(float* c, unsigned a0, unsigned a1, unsigned a2,
                                      unsigned a3, unsigned b0, unsigned b1) {
    asm volatile(
        "mma.sync.aligned.m16n8k16.row.col.f32.bf16.bf16.f32 "
        "{%0,%1,%2,%3},{%4,%5,%6,%7},{%8,%9},{%0,%1,%2,%3};"
        : "+f"(c[0]), "+f"(c[1]), "+f"(c[2]), "+f"(c[3])
        : "r"(a0), "r"(a1), "r"(a2), "r"(a3), "r"(b0), "r"(b1));
}

// ---------------------------------------------------------------- GEMM (persistent, bf16 3-pass)
// Z[row][j] = sum_k a(row,k) * W[j][k]   (bias dropped: exactly absorbed by following BN)
// mode 0: a = Ab;  mode 2: a = relu(sIn*Ab+cIn)
__global__ void __launch_bounds__(512, 1) gemm_bf16(
    const float* __restrict__ Ab, const float* __restrict__ W,
    const float* __restrict__ sIn, const float* __restrict__ cIn,
    int mode, int M, int nTiles,
    float* __restrict__ Z, float* __restrict__ gsum, float* __restrict__ gsq) {
    extern __shared__ unsigned smu[];
    unsigned* Ah = smu;
    unsigned* Al = Ah + 128 * AST;
    unsigned* Wh = Al + 128 * AST;
    unsigned* Wl = Wh + 128 * AST;
    float* csum = (float*)(Wl + 128 * AST);
    float* csq = csum + DD;

    const int tid = threadIdx.x;
    const int lane = tid & 31, w = tid >> 5;
    const int q = lane & 3, mr = lane >> 2;
    const int mw = (w & 7) * 16, nh = w >> 3;

    if (tid < DD) { csum[tid] = 0.f; csq[tid] = 0.f; }

    // W -> Wh/Wl (split bf16, stride AST)
    {
        const float4* w4 = (const float4*)W;
#pragma unroll
        for (int i = 0; i < 8; i++) {
            int f = tid + i * 512;
            int n = f >> 5, c4 = f & 31;
            float4 v = w4[f];
            unsigned h0, l0, h1, l1;
            bsplit2(v.x, v.y, h0, l0);
            bsplit2(v.z, v.w, h1, l1);
            int off = n * AST + 2 * c4;
            *(uint2*)(Wh + off) = make_uint2(h0, h1);
            *(uint2*)(Wl + off) = make_uint2(l0, l1);
        }
    }
    // per-thread affine constants (k fixed per thread: k0 = 4*(tid&31))
    const int k0 = 4 * (tid & 31);
    float s0 = 0.f, s1 = 0.f, s2 = 0.f, s3 = 0.f, cc0 = 0.f, cc1 = 0.f, cc2 = 0.f, cc3 = 0.f;
    if (mode == 2) {
        s0 = __ldg(sIn + k0); s1 = __ldg(sIn + k0 + 1);
        s2 = __ldg(sIn + k0 + 2); s3 = __ldg(sIn + k0 + 3);
        cc0 = __ldg(cIn + k0); cc1 = __ldg(cIn + k0 + 1);
        cc2 = __ldg(cIn + k0 + 2); cc3 = __ldg(cIn + k0 + 3);
    }

    float4 pf[8];
    auto prefetch = [&](int t) {
        size_t rowBase = (size_t)t << 7;
#pragma unroll
        for (int i = 0; i < 8; i++) {
            int f = tid + i * 512;
            int r = f >> 5, c4 = f & 31;
            size_t gr = rowBase + r;
            pf[i] = (gr < (size_t)M) ? *(const float4*)(Ab + gr * DD + c4 * 4)
                                     : make_float4(0.f, 0.f, 0.f, 0.f);
        }
    };

    int tIdx = blockIdx.x;
    if (tIdx < nTiles) prefetch(tIdx);

    for (; tIdx < nTiles; tIdx += gridDim.x) {
        __syncthreads();   // previous tile's compute done reading A smem
        // store A (pre-op + split)
#pragma unroll
        for (int i = 0; i < 8; i++) {
            int f = tid + i * 512;
            int r = f >> 5;
            float4 v = pf[i];
            if (mode == 2) {
                v.x = fmaxf(fmaf(s0, v.x, cc0), 0.f);
                v.y = fmaxf(fmaf(s1, v.y, cc1), 0.f);
                v.z = fmaxf(fmaf(s2, v.z, cc2), 0.f);
                v.w = fmaxf(fmaf(s3, v.w, cc3), 0.f);
            }
            unsigned h0, l0, h1, l1;
            bsplit2(v.x, v.y, h0, l0);
            bsplit2(v.z, v.w, h1, l1);
            int off = r * AST + 2 * (tid & 31);
            *(uint2*)(Ah + off) = make_uint2(h0, h1);
            *(uint2*)(Al + off) = make_uint2(l0, l1);
        }
        __syncthreads();   // A ready
        int rowBase = tIdx << 7;
        if (tIdx + (int)gridDim.x < nTiles) prefetch(tIdx + gridDim.x);   // overlap DRAM w/ mma

        float acc[8][4];
#pragma unroll
        for (int nt = 0; nt < 8; nt++)
#pragma unroll
            for (int j = 0; j < 4; j++) acc[nt][j] = 0.f;

#pragma unroll
        for (int kt = 0; kt < 8; kt++) {
            const int c8 = kt * 8;
            const unsigned* ar = Ah + (mw + mr) * AST + c8 + q;
            unsigned ah0 = ar[0], ah1 = ar[8 * AST], ah2 = ar[4], ah3 = ar[8 * AST + 4];
            const unsigned* al = Al + (mw + mr) * AST + c8 + q;
            unsigned aL0 = al[0], aL1 = al[8 * AST], aL2 = al[4], aL3 = al[8 * AST + 4];
#pragma unroll
            for (int nt = 0; nt < 8; nt++) {
                const int n = nh * 64 + nt * 8 + mr;
                const unsigned* whp = Wh + n * AST + c8 + q;
                unsigned bh0 = whp[0], bh1 = whp[4];
                const unsigned* wlp = Wl + n * AST + c8 + q;
                unsigned bl0 = wlp[0], bl1 = wlp[4];
                mma16(acc[nt], ah0, ah1, ah2, ah3, bh0, bh1);
                mma16(acc[nt], aL0, aL1, aL2, aL3, bh0, bh1);
                mma16(acc[nt], ah0, ah1, ah2, ah3, bl0, bl1);
            }
        }

        // epilogue: store Z + per-column stats
        const int r0 = rowBase + mw + mr;
        const int r1 = r0 + 8;
        const bool ok0 = r0 < M, ok1 = r1 < M;
#pragma unroll
        for (int nt = 0; nt < 8; nt++) {
            int j0 = nh * 64 + nt * 8 + 2 * q;
            float v00 = acc[nt][0], v01 = acc[nt][1], v10 = acc[nt][2], v11 = acc[nt][3];
            if (ok0) *(float2*)(Z + (size_t)r0 * DD + j0) = make_float2(v00, v01);
            if (ok1) *(float2*)(Z + (size_t)r1 * DD + j0) = make_float2(v10, v11);
            float S0 = (ok0 ? v00 : 0.f) + (ok1 ? v10 : 0.f);
            float S1 = (ok0 ? v01 : 0.f) + (ok1 ? v11 : 0.f);
            float Q0 = (ok0 ? v00 * v00 : 0.f) + (ok1 ? v10 * v10 : 0.f);
            float Q1 = (ok0 ? v01 * v01 : 0.f) + (ok1 ? v11 * v11 : 0.f);
#pragma unroll
            for (int m = 4; m <= 16; m <<= 1) {
                S0 += __shfl_xor_sync(0xffffffff, S0, m);
                S1 += __shfl_xor_sync(0xffffffff, S1, m);
                Q0 += __shfl_xor_sync(0xffffffff, Q0, m);
                Q1 += __shfl_xor_sync(0xffffffff, Q1, m);
            }
            if (mr == 0) {
                atomicAdd(&csum[j0], S0);
                atomicAdd(&csum[j0 + 1], S1);
                atomicAdd(&csq[j0], Q0);
                atomicAdd(&csq[j0 + 1], Q1);
            }
        }
    }
    __syncthreads();
    if (tid < DD) {
        atomicAdd(&gsum[tid], csum[tid]);
        atomicAdd(&gsq[tid], csq[tid]);
    }
}

// ---------------------------------------------------------------- BN finalize
__global__ void finalize_kernel(float* __restrict__ gsum, float* __restrict__ gsq,
                                const float* __restrict__ gamma, const float* __restrict__ beta,
                                float invM, float* __restrict__ sOut, float* __restrict__ cOut) {
    int j = threadIdx.x;
    float mean = gsum[j] * invM;
    float var = gsq[j] * invM - mean * mean;
    float s = gamma[j] * rsqrtf(var + 1e-5f);
    sOut[j] = s;
    cOut[j] = beta[j] - mean * s;
    gsum[j] = 0.f;
    gsq[j] = 0.f;
}

// ---------------------------------------------------------------- final apply
__global__ void apply_kernel(const float4* __restrict__ z, const float* __restrict__ s,
                             const float* __restrict__ c, float4* __restrict__ out, int n4) {
    int i = blockIdx.x * blockDim.x + threadIdx.x;
    if (i >= n4) return;
    int k = (i & 31) * 4;
    float4 v = z[i];
    out[i] = make_float4(fmaf(s[k + 0], v.x, c[k + 0]),
                         fmaf(s[k + 1], v.y, c[k + 1]),
                         fmaf(s[k + 2], v.z, c[k + 2]),
                         fmaf(s[k + 3], v.w, c[k + 3]));
}

// ---------------------------------------------------------------- launch
extern "C" void kernel_launch(void* const* d_in, const int* in_sizes, int n_in,
                              void* d_out, int out_size) {
    const float* x    = (const float*)d_in[0];
    const void*  ei   = d_in[1];
    const float* W1   = (const float*)d_in[2];
    const float* g1   = (const float*)d_in[4];
    const float* bt1  = (const float*)d_in[5];
    const float* W2   = (const float*)d_in[6];
    const float* epsv = (const float*)d_in[8];
    const float* gout = (const float*)d_in[9];
    const float* bout = (const float*)d_in[10];

    int N = in_sizes[0] / DD;
    int E = in_sizes[1] / 2;

    void* p;
    cudaGetSymbolAddress(&p, g_aggr); float* aggr = (float*)p;
    cudaGetSymbolAddress(&p, g_z1);   float* z1   = (float*)p;
    cudaGetSymbolAddress(&p, g_z2);   float* z2   = (float*)p;
    cudaGetSymbolAddress(&p, g_idx);  int*   idx  = (int*)p;
    cudaGetSymbolAddress(&p, g_cnt);  int*   cnt  = (int*)p;
    cudaGetSymbolAddress(&p, g_off);  int*   off  = (int*)p;
    cudaGetSymbolAddress(&p, g_cur);  int*   cur  = (int*)p;
    cudaGetSymbolAddress(&p, g_srcl); int*   srcl = (int*)p;
    cudaGetSymbolAddress(&p, g_bsum); int*   bsum = (int*)p;
    cudaGetSymbolAddress(&p, g_sum);  float* gsum = (float*)p;
    cudaGetSymbolAddress(&p, g_sq);   float* gsq  = (float*)p;
    cudaGetSymbolAddress(&p, g_s1);   float* s1   = (float*)p;
    cudaGetSymbolAddress(&p, g_c1);   float* c1   = (float*)p;
    cudaGetSymbolAddress(&p, g_sh);   float* sh   = (float*)p;
    cudaGetSymbolAddress(&p, g_ch);   float* ch   = (float*)p;

    constexpr int SMEM = (4 * 128 * AST + 2 * DD) * 4;   // 140288
    cudaFuncSetAttribute(gemm_bf16, cudaFuncAttributeMaxDynamicSharedMemorySize, SMEM);

    float invM = 1.0f / (float)N;
    int n4 = N * (DD / 4);
    int zb = (n4 + 255) / 256;
    int n2 = 2 * E;
    int cb = (n2 + 255) / 256;
    int eb = (E + 255) / 256;
    int nb = (N + 255) / 256;
    int ab = (N * 32 + 255) / 256;
    int nTiles = (N + 127) / 128;
    int gg = 148;

    detect_kernel<<<1, 64>>>((const int*)ei, E);
    convert_kernel<<<cb, 256>>>(ei, n2, N);

    // CSR build (reused by both layers)
    zcnt_kernel<<<nb, 256>>>(cnt, N);
    hist_kernel<<<eb, 256>>>(idx, E, cnt);
    scan_block<<<nb, 256>>>(cnt, N, cur, bsum);
    scan_sums<<<1, 512>>>(bsum, nb);
    scan_final<<<nb, 256>>>(cur, bsum, cnt, N, off, cur);
    fill_kernel<<<eb, 256>>>(idx, E, cur, srcl);

    // ---- layer 0 ----
    aggregate_kernel<<<ab, 256>>>((const float4*)x, off, srcl, N, (float4*)aggr,
                                  nullptr, nullptr, epsv, 0, 0);
    gemm_bf16<<<gg, 512, SMEM>>>(aggr, W1, nullptr, nullptr, 0, N, nTiles, z1, gsum, gsq);
    finalize_kernel<<<1, DD>>>(gsum, gsq, g1, bt1, invM, s1, c1);
    gemm_bf16<<<gg, 512, SMEM>>>(z1, W2, s1, c1, 2, N, nTiles, z2, gsum, gsq);
    finalize_kernel<<<1, DD>>>(gsum, gsq, gout, bout, invM, sh, ch);

    // ---- layer 1 ----
    aggregate_kernel<<<ab, 256>>>((const float4*)z2, off, srcl, N, (float4*)aggr,
                                  sh, ch, epsv, 1, 1);
    gemm_bf16<<<gg, 512, SMEM>>>(aggr, W1 + DD * DD, nullptr, nullptr, 0, N, nTiles, z1, gsum, gsq);
    finalize_kernel<<<1, DD>>>(gsum, gsq, g1 + DD, bt1 + DD, invM, s1, c1);
    gemm_bf16<<<gg, 512, SMEM>>>(z1, W2 + DD * DD, s1, c1, 2, N, nTiles, z2, gsum, gsq);
    finalize_kernel<<<1, DD>>>(gsum, gsq, gout + DD, bout + DD, invM, sh, ch);

    apply_kernel<<<zb, 256>>>((const float4*)z2, sh, ch, (float4*)d_out, n4);
}